// round 9
// baseline (speedup 1.0000x reference)
#include <cuda_runtime.h>
#include <cstdint>

#define T_LEN 4096
#define E_DIM 1024
#define H_DIM 2048
#define G4    8192      // 4*H
#define NTAGS 128

#define NCTA   128
#define NTHR   512
#define NWARPS 16
#define W2_CACHE 5           // warps 0..4 keep their W2 row in smem; ALL W1 rows cached
#define W1_ROW 8192          // bytes: 4 gates * 2048 int8
#define W2_ROW 16384         // bytes: 4 gates * 4096 int8
#define SMEM_BYTES (4096 + NWARPS*W1_ROW + W2_CACHE*W2_ROW)   // 217088

// ---------------- static device buffers ----------------
__device__ __align__(16) signed char g_W1q[(size_t)H_DIM * W1_ROW];   // [j][g][k]
__device__ __align__(16) signed char g_W2q[(size_t)H_DIM * W2_ROW];   // [j][g][kk]
__device__ __align__(16) float g_s1[H_DIM * 4];
__device__ __align__(16) float g_s2[H_DIM * 4];
__device__ __align__(16) float g_P[(size_t)T_LEN * G4];
__device__ __align__(16) float g_b2[G4];
__device__ __align__(16) signed char g_h1q[2][H_DIM];
__device__ __align__(16) signed char g_h2q[2][H_DIM];
__device__ __align__(16) float g_h2f[H_DIM];
__device__ __align__(16) float g_tag[NTAGS];
__device__ unsigned g_count;             // barrier arrival counter (reset each launch in k0)

// ---------------- helpers ----------------
__device__ __forceinline__ unsigned ld_acq(unsigned* a) {
    unsigned v;
    asm volatile("ld.acquire.gpu.global.u32 %0, [%1];" : "=r"(v) : "l"(a) : "memory");
    return v;
}
__device__ __forceinline__ float sigf(float x) { return 1.0f / (1.0f + __expf(-x)); }
__device__ __forceinline__ float tanhfast(float x) {
    float e = __expf(2.0f * x);
    return 1.0f - __fdividef(2.0f, e + 1.0f);
}

__device__ __forceinline__ int dotq(int acc, int4 wv, int4 hv) {
    acc = __dp4a(wv.x, hv.x, acc);
    acc = __dp4a(wv.y, hv.y, acc);
    acc = __dp4a(wv.z, hv.z, acc);
    acc = __dp4a(wv.w, hv.w, acc);
    return acc;
}

// 4-gate int8 dot from SMEM: wp row base ([g][k], gate stride GS bytes), hp = h vector
template<int NC, int GS>
__device__ __forceinline__ void dot4(const signed char* wp, const signed char* hp, int lane,
                                     int& a0, int& a1, int& a2, int& a3) {
    int off = lane * 16;
    #pragma unroll
    for (int c = 0; c < NC; c++, off += 512) {
        int4 hv = *(const int4*)(hp + off);
        int4 w0 = *(const int4*)(wp + off);
        int4 w1 = *(const int4*)(wp + GS + off);
        int4 w2 = *(const int4*)(wp + 2 * GS + off);
        int4 w3 = *(const int4*)(wp + 3 * GS + off);
        a0 = dotq(a0, w0, hv);
        a1 = dotq(a1, w1, hv);
        a2 = dotq(a2, w2, hv);
        a3 = dotq(a3, w3, hv);
    }
}

// W2 dot from GMEM (gate stride 4096B, 8 chunks): 2-chunk register lookahead so only
// one L2 latency is exposed instead of ~8 serialized round trips.
__device__ __forceinline__ void dot4_g2(const signed char* wp, const signed char* hp, int lane,
                                        int& a0, int& a1, int& a2, int& a3) {
    int off = lane * 16;
    int4 w00, w01, w02, w03, w10, w11, w12, w13;
    int4 n00, n01, n02, n03, n10, n11, n12, n13;
    // batch 0: chunks 0,1 (8 independent LDG.128)
    w00 = *(const int4*)(wp + off);               w01 = *(const int4*)(wp + 4096 + off);
    w02 = *(const int4*)(wp + 8192 + off);        w03 = *(const int4*)(wp + 12288 + off);
    w10 = *(const int4*)(wp + off + 512);         w11 = *(const int4*)(wp + 4096 + off + 512);
    w12 = *(const int4*)(wp + 8192 + off + 512);  w13 = *(const int4*)(wp + 12288 + off + 512);
    #pragma unroll
    for (int b = 0; b < 4; b++) {
        int noff = off + 1024;
        if (b < 3) {  // prefetch next batch before consuming current
            n00 = *(const int4*)(wp + noff);               n01 = *(const int4*)(wp + 4096 + noff);
            n02 = *(const int4*)(wp + 8192 + noff);        n03 = *(const int4*)(wp + 12288 + noff);
            n10 = *(const int4*)(wp + noff + 512);         n11 = *(const int4*)(wp + 4096 + noff + 512);
            n12 = *(const int4*)(wp + 8192 + noff + 512);  n13 = *(const int4*)(wp + 12288 + noff + 512);
        }
        int4 hv0 = *(const int4*)(hp + off);
        int4 hv1 = *(const int4*)(hp + off + 512);
        a0 = dotq(a0, w00, hv0); a1 = dotq(a1, w01, hv0);
        a2 = dotq(a2, w02, hv0); a3 = dotq(a3, w03, hv0);
        a0 = dotq(a0, w10, hv1); a1 = dotq(a1, w11, hv1);
        a2 = dotq(a2, w12, hv1); a3 = dotq(a3, w13, hv1);
        w00 = n00; w01 = n01; w02 = n02; w03 = n03;
        w10 = n10; w11 = n11; w12 = n12; w13 = n13;
        off = noff;
    }
}

// packed f32x2 helpers (sm_100a dual-issue FMA)
__device__ __forceinline__ unsigned long long pack2(float x, float y) {
    unsigned long long r;
    asm("mov.b64 %0, {%1, %2};" : "=l"(r) : "f"(x), "f"(y));
    return r;
}
__device__ __forceinline__ void fma2(unsigned long long& d, unsigned long long a, unsigned long long b) {
    asm("fma.rn.f32x2 %0, %1, %2, %0;" : "+l"(d) : "l"(a), "l"(b));
}
__device__ __forceinline__ float2 unpack2(unsigned long long v) {
    float2 r;
    asm("mov.b64 {%0, %1}, %2;" : "=f"(r.x), "=f"(r.y) : "l"(v));
    return r;
}

// ---------------- K0: quantize weights (fp32 -> int8 row-scaled) + misc init ----------------
__global__ void k0_quant(const float* __restrict__ Whh1,
                         const float* __restrict__ Wih2, const float* __restrict__ Whh2,
                         const float* __restrict__ bih2, const float* __restrict__ bhh2) {
    const int tid  = blockIdx.x * blockDim.x + threadIdx.x;
    const int nt   = gridDim.x * blockDim.x;
    const int gw   = tid >> 5;
    const int nw   = nt >> 5;
    const int lane = threadIdx.x & 31;

    // layer 1: 8192 gate-rows of 2048
    for (int r = gw; r < 8192; r += nw) {
        int j = r >> 2, g = r & 3;
        const float* src = Whh1 + (size_t)(g * H_DIM + j) * H_DIM;
        float m = 0.f;
        #pragma unroll 4
        for (int c = 0; c < 16; c++) {
            float4 v = *(const float4*)(src + c * 128 + lane * 4);
            m = fmaxf(m, fmaxf(fmaxf(fabsf(v.x), fabsf(v.y)), fmaxf(fabsf(v.z), fabsf(v.w))));
        }
        #pragma unroll
        for (int o = 16; o; o >>= 1) m = fmaxf(m, __shfl_xor_sync(0xffffffffu, m, o));
        float inv = (m > 0.f) ? 127.f / m : 0.f;
        signed char* dst = g_W1q + (size_t)j * W1_ROW + g * H_DIM;
        #pragma unroll 4
        for (int c = 0; c < 16; c++) {
            float4 v = *(const float4*)(src + c * 128 + lane * 4);
            int pk = (__float2int_rn(v.x * inv) & 255)
                   | ((__float2int_rn(v.y * inv) & 255) << 8)
                   | ((__float2int_rn(v.z * inv) & 255) << 16)
                   | ((__float2int_rn(v.w * inv) & 255) << 24);
            *(int*)(dst + c * 128 + lane * 4) = pk;
        }
        if (lane == 0) g_s1[j * 4 + g] = m / 16129.f;
    }

    // layer 2: 8192 gate-rows of 4096 (Wih2 | Whh2 concat)
    for (int r = gw; r < 8192; r += nw) {
        int j = r >> 2, g = r & 3;
        const float* sA = Wih2 + (size_t)(g * H_DIM + j) * H_DIM;
        const float* sB = Whh2 + (size_t)(g * H_DIM + j) * H_DIM;
        float m = 0.f;
        #pragma unroll 4
        for (int c = 0; c < 16; c++) {
            float4 v = *(const float4*)(sA + c * 128 + lane * 4);
            m = fmaxf(m, fmaxf(fmaxf(fabsf(v.x), fabsf(v.y)), fmaxf(fabsf(v.z), fabsf(v.w))));
        }
        #pragma unroll 4
        for (int c = 0; c < 16; c++) {
            float4 v = *(const float4*)(sB + c * 128 + lane * 4);
            m = fmaxf(m, fmaxf(fmaxf(fabsf(v.x), fabsf(v.y)), fmaxf(fabsf(v.z), fabsf(v.w))));
        }
        #pragma unroll
        for (int o = 16; o; o >>= 1) m = fmaxf(m, __shfl_xor_sync(0xffffffffu, m, o));
        float inv = (m > 0.f) ? 127.f / m : 0.f;
        signed char* dst = g_W2q + (size_t)j * W2_ROW + g * 2 * H_DIM;
        #pragma unroll 4
        for (int c = 0; c < 16; c++) {
            float4 v = *(const float4*)(sA + c * 128 + lane * 4);
            int pk = (__float2int_rn(v.x * inv) & 255)
                   | ((__float2int_rn(v.y * inv) & 255) << 8)
                   | ((__float2int_rn(v.z * inv) & 255) << 16)
                   | ((__float2int_rn(v.w * inv) & 255) << 24);
            *(int*)(dst + c * 128 + lane * 4) = pk;
        }
        #pragma unroll 4
        for (int c = 0; c < 16; c++) {
            float4 v = *(const float4*)(sB + c * 128 + lane * 4);
            int pk = (__float2int_rn(v.x * inv) & 255)
                   | ((__float2int_rn(v.y * inv) & 255) << 8)
                   | ((__float2int_rn(v.z * inv) & 255) << 16)
                   | ((__float2int_rn(v.w * inv) & 255) << 24);
            *(int*)(dst + H_DIM + c * 128 + lane * 4) = pk;
        }
        if (lane == 0) g_s2[j * 4 + g] = m / 16129.f;
    }

    for (int i = tid; i < G4; i += nt) g_b2[i] = bih2[i] + bhh2[i];
    for (int i = tid; i < H_DIM; i += nt) {
        g_h1q[0][i] = 0; g_h1q[1][i] = 0;
        g_h2q[0][i] = 0; g_h2q[1][i] = 0;
    }
    if (tid == 0) g_count = 0u;
}

// ---------------- K1: P = x @ W_ih1^T + (b_ih1 + b_hh1), f32x2-packed GEMM ----------------
__global__ void __launch_bounds__(256) k1_gemm(const float* __restrict__ X,
                                               const float* __restrict__ W,
                                               const float* __restrict__ b1,
                                               const float* __restrict__ b2) {
    __shared__ float As[16][132];
    __shared__ float Bs[16][132];

    const int t  = threadIdx.x;
    const int tx = t % 16, ty = t / 16;
    const int m0 = blockIdx.y * 128;
    const int n0 = blockIdx.x * 128;
    const int rl = t / 4;
    const int kq = (t % 4) * 4;

    unsigned long long acc2[4][8];
    #pragma unroll
    for (int i = 0; i < 4; i++)
        #pragma unroll
        for (int j = 0; j < 8; j++) acc2[i][j] = 0ull;

    for (int kt = 0; kt < E_DIM; kt += 16) {
        float4 a0 = *(const float4*)(X + (size_t)(m0 + rl)      * E_DIM + kt + kq);
        float4 a1 = *(const float4*)(X + (size_t)(m0 + rl + 64) * E_DIM + kt + kq);
        float4 w0 = *(const float4*)(W + (size_t)(n0 + rl)      * E_DIM + kt + kq);
        float4 w1 = *(const float4*)(W + (size_t)(n0 + rl + 64) * E_DIM + kt + kq);
        __syncthreads();
        As[kq+0][rl] = a0.x; As[kq+1][rl] = a0.y; As[kq+2][rl] = a0.z; As[kq+3][rl] = a0.w;
        As[kq+0][rl+64] = a1.x; As[kq+1][rl+64] = a1.y; As[kq+2][rl+64] = a1.z; As[kq+3][rl+64] = a1.w;
        Bs[kq+0][rl] = w0.x; Bs[kq+1][rl] = w0.y; Bs[kq+2][rl] = w0.z; Bs[kq+3][rl] = w0.w;
        Bs[kq+0][rl+64] = w1.x; Bs[kq+1][rl+64] = w1.y; Bs[kq+2][rl+64] = w1.z; Bs[kq+3][rl+64] = w1.w;
        __syncthreads();
        #pragma unroll
        for (int kk = 0; kk < 16; kk++) {
            ulonglong2 p0 = *(const ulonglong2*)&As[kk][ty*8];
            ulonglong2 p1 = *(const ulonglong2*)&As[kk][ty*8 + 4];
            unsigned long long a2[4] = {p0.x, p0.y, p1.x, p1.y};
            float b[8];
            *(float4*)(b)     = *(const float4*)&Bs[kk][tx*8];
            *(float4*)(b + 4) = *(const float4*)&Bs[kk][tx*8 + 4];
            unsigned long long bb[8];
            #pragma unroll
            for (int j = 0; j < 8; j++) bb[j] = pack2(b[j], b[j]);
            #pragma unroll
            for (int i = 0; i < 4; i++)
                #pragma unroll
                for (int j = 0; j < 8; j++)
                    fma2(acc2[i][j], a2[i], bb[j]);
        }
    }

    float bs[8];
    #pragma unroll
    for (int j = 0; j < 8; j++) {
        int n = n0 + tx*8 + j;
        bs[j] = __ldg(&b1[n]) + __ldg(&b2[n]);
    }
    #pragma unroll
    for (int i2 = 0; i2 < 4; i2++) {
        float lo[8], hi[8];
        #pragma unroll
        for (int j = 0; j < 8; j++) {
            float2 v = unpack2(acc2[i2][j]);
            lo[j] = v.x + bs[j];
            hi[j] = v.y + bs[j];
        }
        int mA = m0 + ty*8 + 2*i2;
        float* dA = g_P + (size_t)mA * G4 + n0 + tx*8;
        float* dB = dA + G4;
        __stcs((float4*)dA,       make_float4(lo[0], lo[1], lo[2], lo[3]));
        __stcs((float4*)(dA + 4), make_float4(lo[4], lo[5], lo[6], lo[7]));
        __stcs((float4*)dB,       make_float4(hi[0], hi[1], hi[2], hi[3]));
        __stcs((float4*)(dB + 4), make_float4(hi[4], hi[5], hi[6], hi[7]));
    }
}

// ---------------- K2: persistent int8 recurrent kernel ----------------
__global__ void __launch_bounds__(NTHR, 1) k2_recur() {
    extern __shared__ __align__(16) signed char smem[];
    signed char* shv = smem;                         // 4096: h1q(2048) | h2q(2048)
    signed char* sW1 = smem + 4096;                  // 16 rows * 8KB (ALL warps)
    signed char* sW2 = sW1 + NWARPS * W1_ROW;        // 5 rows * 16KB (warps 0..4)

    const int tid  = threadIdx.x;
    const int warp = tid >> 5;
    const int lane = tid & 31;
    const int w    = blockIdx.x * NWARPS + warp;     // owned h-row, both layers

    // pin weight rows in SMEM: every warp pins its W1 row; warps 0..4 also pin W2
    {
        const int4* src = (const int4*)(g_W1q + (size_t)w * W1_ROW);
        int4* dst = (int4*)(sW1 + (size_t)warp * W1_ROW);
        #pragma unroll
        for (int i = 0; i < 16; i++) dst[lane + i * 32] = src[lane + i * 32];
    }
    if (warp < W2_CACHE) {
        const int4* src = (const int4*)(g_W2q + (size_t)w * W2_ROW);
        int4* dst = (int4*)(sW2 + (size_t)warp * W2_ROW);
        #pragma unroll
        for (int i = 0; i < 32; i++) dst[lane + i * 32] = src[lane + i * 32];
    }

    const float4 fs1 = *(const float4*)(g_s1 + w * 4);
    const float4 fs2 = *(const float4*)(g_s2 + w * 4);
    const float bi = g_b2[w], bf = g_b2[w + H_DIM], bg = g_b2[w + 2*H_DIM], bo = g_b2[w + 3*H_DIM];

    float c1 = 0.f, c2 = 0.f;

    for (int p = 0; p <= T_LEN; p++) {
        // prefetch this step's P early (independent of the staged h)
        float p0 = 0.f, p1 = 0.f, p2 = 0.f, p3 = 0.f;
        if (lane == 0 && p < T_LEN) {
            size_t pb = (size_t)p * G4 + w;
            p0 = __ldcs(&g_P[pb]);
            p1 = __ldcs(&g_P[pb + H_DIM]);
            p2 = __ldcs(&g_P[pb + 2*H_DIM]);
            p3 = __ldcs(&g_P[pb + 3*H_DIM]);
        }

        // stage h vectors: shv[0:2048]=h1q_{p-1}, shv[2048:4096]=h2q_{p-2}
        {
            const int2* s1 = (const int2*)g_h1q[p & 1];
            const int2* s2 = (const int2*)g_h2q[(p + 1) & 1];
            if (tid < 256) ((int2*)shv)[tid] = __ldcg(s1 + tid);
            else           ((int2*)shv)[tid] = __ldcg(s2 + (tid - 256));
        }
        __syncthreads();

        // -------- layer 1, step t = p (W1 always in SMEM) --------
        if (p < T_LEN) {
            int a0 = 0, a1 = 0, a2 = 0, a3 = 0;
            dot4<4, H_DIM>(sW1 + (size_t)warp * W1_ROW, shv, lane, a0, a1, a2, a3);
            a0 = __reduce_add_sync(0xffffffffu, a0);
            a1 = __reduce_add_sync(0xffffffffu, a1);
            a2 = __reduce_add_sync(0xffffffffu, a2);
            a3 = __reduce_add_sync(0xffffffffu, a3);
            if (lane == 0) {
                float gi  = (float)a0 * fs1.x + p0;
                float gf_ = (float)a1 * fs1.y + p1;
                float gg  = (float)a2 * fs1.z + p2;
                float go_ = (float)a3 * fs1.w + p3;
                c1 = sigf(gf_) * c1 + sigf(gi) * tanhfast(gg);
                float h = sigf(go_) * tanhfast(c1);
                g_h1q[(p + 1) & 1][w] = (signed char)__float2int_rn(h * 127.f);
            }
        }

        // -------- layer 2, step t = p-1 (input [h1q_{p-1} ; h2q_{p-2}] = shv) --------
        if (p >= 1) {
            int a0 = 0, a1 = 0, a2 = 0, a3 = 0;
            if (warp < W2_CACHE)
                dot4<8, 2*H_DIM>(sW2 + (size_t)warp * W2_ROW, shv, lane, a0, a1, a2, a3);
            else
                dot4_g2(g_W2q + (size_t)w * W2_ROW, shv, lane, a0, a1, a2, a3);
            a0 = __reduce_add_sync(0xffffffffu, a0);
            a1 = __reduce_add_sync(0xffffffffu, a1);
            a2 = __reduce_add_sync(0xffffffffu, a2);
            a3 = __reduce_add_sync(0xffffffffu, a3);
            if (lane == 0) {
                float gi  = (float)a0 * fs2.x + bi;
                float gf_ = (float)a1 * fs2.y + bf;
                float gg  = (float)a2 * fs2.z + bg;
                float go_ = (float)a3 * fs2.w + bo;
                c2 = sigf(gf_) * c2 + sigf(gi) * tanhfast(gg);
                float h = sigf(go_) * tanhfast(c2);
                g_h2q[p & 1][w] = (signed char)__float2int_rn(h * 127.f);
                if (p == T_LEN) g_h2f[w] = h;
            }
        }

        // -------- grid barrier: fence + atomicAdd arrive, single-word acquire poll --------
        __syncthreads();
        if (tid == 0) {
            __threadfence();                         // release: publish h-state stores
            atomicAdd(&g_count, 1u);
            unsigned tgt = (unsigned)(p + 1) * (unsigned)NCTA;
            while (ld_acq(&g_count) < tgt) { }
        }
        __syncthreads();
    }
}

// ---------------- K3a: tag_space = h2 @ W_out^T + b_out (one block per tag) ----------------
__global__ void k3a(const float* __restrict__ Wout, const float* __restrict__ bout) {
    __shared__ float red[256];
    const int b = blockIdx.x, t = threadIdx.x;
    float acc = 0.f;
    #pragma unroll
    for (int c = 0; c < 2; c++) {
        float4 wv = *(const float4*)(Wout + (size_t)b * H_DIM + c * 1024 + t * 4);
        float4 hv = *(const float4*)(g_h2f + c * 1024 + t * 4);
        acc += wv.x * hv.x + wv.y * hv.y + wv.z * hv.z + wv.w * hv.w;
    }
    red[t] = acc;
    __syncthreads();
    #pragma unroll
    for (int s = 128; s; s >>= 1) {
        if (t < s) red[t] += red[t + s];
        __syncthreads();
    }
    if (t == 0) g_tag[b] = red[0] + bout[b];
}

// ---------------- K3b: log_softmax ----------------
__global__ void k3b(float* __restrict__ out) {
    __shared__ float st[NTAGS];
    __shared__ float m_s, l_s;
    const int t = threadIdx.x;
    float v = g_tag[t];
    st[t] = v;
    __syncthreads();
    if (t == 0) {
        float m = st[0];
        for (int i = 1; i < NTAGS; i++) m = fmaxf(m, st[i]);
        float s = 0.f;
        for (int i = 0; i < NTAGS; i++) s += expf(st[i] - m);
        m_s = m;
        l_s = logf(s);
    }
    __syncthreads();
    out[t] = v - m_s - l_s;
}

// ---------------- launch ----------------
extern "C" void kernel_launch(void* const* d_in, const int* in_sizes, int n_in,
                              void* d_out, int out_size) {
    const float* x    = (const float*)d_in[0];
    const float* Wih1 = (const float*)d_in[1];
    const float* Whh1 = (const float*)d_in[2];
    const float* bih1 = (const float*)d_in[3];
    const float* bhh1 = (const float*)d_in[4];
    const float* Wih2 = (const float*)d_in[5];
    const float* Whh2 = (const float*)d_in[6];
    const float* bih2 = (const float*)d_in[7];
    const float* bhh2 = (const float*)d_in[8];
    const float* Wout = (const float*)d_in[9];
    const float* bout = (const float*)d_in[10];

    cudaFuncSetAttribute(k2_recur, cudaFuncAttributeMaxDynamicSharedMemorySize, SMEM_BYTES);

    k0_quant<<<512, 256>>>(Whh1, Wih2, Whh2, bih2, bhh2);

    dim3 g1(G4 / 128, T_LEN / 128);
    k1_gemm<<<g1, 256>>>(x, Wih1, bih1, bhh1);

    k2_recur<<<NCTA, NTHR, SMEM_BYTES>>>();

    k3a<<<NTAGS, 256>>>(Wout, bout);
    k3b<<<1, NTAGS>>>((float*)d_out);
}

// round 10
// speedup vs baseline: 1.0610x; 1.0610x over previous
#include <cuda_runtime.h>
#include <cuda_bf16.h>
#include <cstdint>

#define T_LEN 4096
#define E_DIM 1024
#define H_DIM 2048
#define G4    8192      // 4*H
#define NTAGS 128

#define NCTA   128
#define NTHR   512
#define NWARPS 16
#define W1_CACHE 15          // warps 0..14 keep their W1 row in smem
#define W2_CACHE 6           // warps 0..5 keep their W2 row in smem
#define W1_ROW 8192          // bytes: 4 gates * 2048 int8
#define W2_ROW 16384         // bytes: 4 gates * 4096 int8
#define SMEM_BYTES (4096 + W1_CACHE*W1_ROW + W2_CACHE*W2_ROW)   // 225280

// ---------------- static device buffers ----------------
__device__ __align__(16) signed char g_W1q[(size_t)H_DIM * W1_ROW];   // [j][g][k]
__device__ __align__(16) signed char g_W2q[(size_t)H_DIM * W2_ROW];   // [j][g][kk]
__device__ __align__(16) float g_s1[H_DIM * 4];
__device__ __align__(16) float g_s2[H_DIM * 4];
__device__ __align__(16) float g_P[(size_t)T_LEN * G4];
__device__ __align__(16) float g_b2[G4];
__device__ __align__(16) signed char g_h1q[2][H_DIM];
__device__ __align__(16) signed char g_h2q[2][H_DIM];
__device__ __align__(16) float g_h2f[H_DIM];
__device__ __align__(16) float g_tag[NTAGS];
__device__ unsigned g_count;             // barrier arrival counter (reset each launch in k0)

// ---------------- helpers ----------------
__device__ __forceinline__ unsigned ld_acq(unsigned* a) {
    unsigned v;
    asm volatile("ld.acquire.gpu.global.u32 %0, [%1];" : "=r"(v) : "l"(a) : "memory");
    return v;
}
__device__ __forceinline__ float sigf(float x) { return 1.0f / (1.0f + __expf(-x)); }
__device__ __forceinline__ float tanhfast(float x) {
    float e = __expf(2.0f * x);
    return 1.0f - __fdividef(2.0f, e + 1.0f);
}

__device__ __forceinline__ int dotq(int acc, int4 wv, int4 hv) {
    acc = __dp4a(wv.x, hv.x, acc);
    acc = __dp4a(wv.y, hv.y, acc);
    acc = __dp4a(wv.z, hv.z, acc);
    acc = __dp4a(wv.w, hv.w, acc);
    return acc;
}

// 4-gate int8 dot: wp = row base ([g][k] layout, gate stride GS bytes), hp = h vector
template<int NC, int GS>
__device__ __forceinline__ void dot4(const signed char* wp, const signed char* hp, int lane,
                                     int& a0, int& a1, int& a2, int& a3) {
    int off = lane * 16;
    #pragma unroll
    for (int c = 0; c < NC; c++, off += 512) {
        int4 hv = *(const int4*)(hp + off);
        int4 w0 = *(const int4*)(wp + off);
        int4 w1 = *(const int4*)(wp + GS + off);
        int4 w2 = *(const int4*)(wp + 2 * GS + off);
        int4 w3 = *(const int4*)(wp + 3 * GS + off);
        a0 = dotq(a0, w0, hv);
        a1 = dotq(a1, w1, hv);
        a2 = dotq(a2, w2, hv);
        a3 = dotq(a3, w3, hv);
    }
}

// ---------------- K0: quantize weights (fp32 -> int8 row-scaled) + misc init ----------------
__global__ void k0_quant(const float* __restrict__ Whh1,
                         const float* __restrict__ Wih2, const float* __restrict__ Whh2,
                         const float* __restrict__ bih2, const float* __restrict__ bhh2) {
    const int tid  = blockIdx.x * blockDim.x + threadIdx.x;
    const int nt   = gridDim.x * blockDim.x;
    const int gw   = tid >> 5;
    const int nw   = nt >> 5;
    const int lane = threadIdx.x & 31;

    // layer 1: 8192 gate-rows of 2048
    for (int r = gw; r < 8192; r += nw) {
        int j = r >> 2, g = r & 3;
        const float* src = Whh1 + (size_t)(g * H_DIM + j) * H_DIM;
        float m = 0.f;
        #pragma unroll 4
        for (int c = 0; c < 16; c++) {
            float4 v = *(const float4*)(src + c * 128 + lane * 4);
            m = fmaxf(m, fmaxf(fmaxf(fabsf(v.x), fabsf(v.y)), fmaxf(fabsf(v.z), fabsf(v.w))));
        }
        #pragma unroll
        for (int o = 16; o; o >>= 1) m = fmaxf(m, __shfl_xor_sync(0xffffffffu, m, o));
        float inv = (m > 0.f) ? 127.f / m : 0.f;
        signed char* dst = g_W1q + (size_t)j * W1_ROW + g * H_DIM;
        #pragma unroll 4
        for (int c = 0; c < 16; c++) {
            float4 v = *(const float4*)(src + c * 128 + lane * 4);
            int pk = (__float2int_rn(v.x * inv) & 255)
                   | ((__float2int_rn(v.y * inv) & 255) << 8)
                   | ((__float2int_rn(v.z * inv) & 255) << 16)
                   | ((__float2int_rn(v.w * inv) & 255) << 24);
            *(int*)(dst + c * 128 + lane * 4) = pk;
        }
        if (lane == 0) g_s1[j * 4 + g] = m / 16129.f;
    }

    // layer 2: 8192 gate-rows of 4096 (Wih2 | Whh2 concat)
    for (int r = gw; r < 8192; r += nw) {
        int j = r >> 2, g = r & 3;
        const float* sA = Wih2 + (size_t)(g * H_DIM + j) * H_DIM;
        const float* sB = Whh2 + (size_t)(g * H_DIM + j) * H_DIM;
        float m = 0.f;
        #pragma unroll 4
        for (int c = 0; c < 16; c++) {
            float4 v = *(const float4*)(sA + c * 128 + lane * 4);
            m = fmaxf(m, fmaxf(fmaxf(fabsf(v.x), fabsf(v.y)), fmaxf(fabsf(v.z), fabsf(v.w))));
        }
        #pragma unroll 4
        for (int c = 0; c < 16; c++) {
            float4 v = *(const float4*)(sB + c * 128 + lane * 4);
            m = fmaxf(m, fmaxf(fmaxf(fabsf(v.x), fabsf(v.y)), fmaxf(fabsf(v.z), fabsf(v.w))));
        }
        #pragma unroll
        for (int o = 16; o; o >>= 1) m = fmaxf(m, __shfl_xor_sync(0xffffffffu, m, o));
        float inv = (m > 0.f) ? 127.f / m : 0.f;
        signed char* dst = g_W2q + (size_t)j * W2_ROW + g * 2 * H_DIM;
        #pragma unroll 4
        for (int c = 0; c < 16; c++) {
            float4 v = *(const float4*)(sA + c * 128 + lane * 4);
            int pk = (__float2int_rn(v.x * inv) & 255)
                   | ((__float2int_rn(v.y * inv) & 255) << 8)
                   | ((__float2int_rn(v.z * inv) & 255) << 16)
                   | ((__float2int_rn(v.w * inv) & 255) << 24);
            *(int*)(dst + c * 128 + lane * 4) = pk;
        }
        #pragma unroll 4
        for (int c = 0; c < 16; c++) {
            float4 v = *(const float4*)(sB + c * 128 + lane * 4);
            int pk = (__float2int_rn(v.x * inv) & 255)
                   | ((__float2int_rn(v.y * inv) & 255) << 8)
                   | ((__float2int_rn(v.z * inv) & 255) << 16)
                   | ((__float2int_rn(v.w * inv) & 255) << 24);
            *(int*)(dst + H_DIM + c * 128 + lane * 4) = pk;
        }
        if (lane == 0) g_s2[j * 4 + g] = m / 16129.f;
    }

    for (int i = tid; i < G4; i += nt) g_b2[i] = bih2[i] + bhh2[i];
    for (int i = tid; i < H_DIM; i += nt) {
        g_h1q[0][i] = 0; g_h1q[1][i] = 0;
        g_h2q[0][i] = 0; g_h2q[1][i] = 0;
    }
    if (tid == 0) g_count = 0u;
}

// ---------------- K1: P = x @ W_ih1^T + bias via bf16 tensor-core MMA ----------------
// Tile 128x128x32; 8 warps in 2(M)x4(N); warp tile 64x32 = 4x4 mma m16n8k16.
__device__ __forceinline__ uint32_t pbf2(float lo, float hi) {
    __nv_bfloat162 h = __floats2bfloat162_rn(lo, hi);
    return *(uint32_t*)&h;
}
__device__ __forceinline__ void ldm_x4(uint32_t& r0, uint32_t& r1, uint32_t& r2, uint32_t& r3,
                                       uint32_t addr) {
    asm volatile("ldmatrix.sync.aligned.m8n8.x4.shared.b16 {%0,%1,%2,%3}, [%4];"
                 : "=r"(r0), "=r"(r1), "=r"(r2), "=r"(r3) : "r"(addr));
}
__device__ __forceinline__ void mma_bf16(float* d, const uint32_t* a, uint32_t b0, uint32_t b1) {
    asm volatile("mma.sync.aligned.m16n8k16.row.col.f32.bf16.bf16.f32 "
                 "{%0,%1,%2,%3}, {%4,%5,%6,%7}, {%8,%9}, {%0,%1,%2,%3};"
                 : "+f"(d[0]), "+f"(d[1]), "+f"(d[2]), "+f"(d[3])
                 : "r"(a[0]), "r"(a[1]), "r"(a[2]), "r"(a[3]), "r"(b0), "r"(b1));
}

#define K1_STRIDE 40   // bf16 elements per smem row (32 data + 8 pad = 80B, 16B-aligned, conflict-free)

__global__ void __launch_bounds__(256) k1_mma(const float* __restrict__ X,
                                              const float* __restrict__ W,
                                              const float* __restrict__ b1,
                                              const float* __restrict__ b2) {
    __shared__ __align__(16) __nv_bfloat16 sA[128 * K1_STRIDE];
    __shared__ __align__(16) __nv_bfloat16 sB[128 * K1_STRIDE];

    const int t    = threadIdx.x;
    const int warp = t >> 5;
    const int lane = t & 31;
    const int wm   = warp >> 2;      // 0..1
    const int wn   = warp & 3;       // 0..3
    const int m0   = blockIdx.y * 128;
    const int n0   = blockIdx.x * 128;

    const int lr = t >> 1;           // load row 0..127
    const int lc = (t & 1) * 16;     // load col half: 0 or 16

    float acc[4][4][4];
    #pragma unroll
    for (int i = 0; i < 4; i++)
        #pragma unroll
        for (int j = 0; j < 4; j++)
            #pragma unroll
            for (int q = 0; q < 4; q++) acc[i][j][q] = 0.f;

    uint32_t sA_base = (uint32_t)__cvta_generic_to_shared(sA);
    uint32_t sB_base = (uint32_t)__cvta_generic_to_shared(sB);

    for (int kt = 0; kt < E_DIM; kt += 32) {
        // load 16 fp32 each from X and W, convert to bf16
        const float4* xs = (const float4*)(X + (size_t)(m0 + lr) * E_DIM + kt + lc);
        const float4* ws = (const float4*)(W + (size_t)(n0 + lr) * E_DIM + kt + lc);
        float4 x0 = xs[0], x1 = xs[1], x2 = xs[2], x3 = xs[3];
        float4 w0 = ws[0], w1 = ws[1], w2 = ws[2], w3 = ws[3];
        __syncthreads();
        {
            uint4 pa, pb;
            pa.x = pbf2(x0.x, x0.y); pa.y = pbf2(x0.z, x0.w);
            pa.z = pbf2(x1.x, x1.y); pa.w = pbf2(x1.z, x1.w);
            pb.x = pbf2(x2.x, x2.y); pb.y = pbf2(x2.z, x2.w);
            pb.z = pbf2(x3.x, x3.y); pb.w = pbf2(x3.z, x3.w);
            *(uint4*)(sA + lr * K1_STRIDE + lc)     = pa;
            *(uint4*)(sA + lr * K1_STRIDE + lc + 8) = pb;
            pa.x = pbf2(w0.x, w0.y); pa.y = pbf2(w0.z, w0.w);
            pa.z = pbf2(w1.x, w1.y); pa.w = pbf2(w1.z, w1.w);
            pb.x = pbf2(w2.x, w2.y); pb.y = pbf2(w2.z, w2.w);
            pb.z = pbf2(w3.x, w3.y); pb.w = pbf2(w3.z, w3.w);
            *(uint4*)(sB + lr * K1_STRIDE + lc)     = pa;
            *(uint4*)(sB + lr * K1_STRIDE + lc + 8) = pb;
        }
        __syncthreads();

        #pragma unroll
        for (int ks = 0; ks < 2; ks++) {
            // A fragments: 4 m-tiles of 16x16
            uint32_t af[4][4];
            #pragma unroll
            for (int mt = 0; mt < 4; mt++) {
                int row = wm * 64 + mt * 16 + (lane & 15);
                uint32_t addr = sA_base + (uint32_t)(row * K1_STRIDE + ks * 16 + (lane >> 4) * 8) * 2u;
                ldm_x4(af[mt][0], af[mt][1], af[mt][2], af[mt][3], addr);
            }
            // B fragments: 2 ldmatrix.x4 cover 4 n8-tiles (W is k-contiguous => col-major B, no trans)
            uint32_t bf[4][2];
            #pragma unroll
            for (int bt = 0; bt < 2; bt++) {
                int row = wn * 32 + bt * 16 + (lane & 15);
                uint32_t addr = sB_base + (uint32_t)(row * K1_STRIDE + ks * 16 + (lane >> 4) * 8) * 2u;
                uint32_t q0, q1, q2, q3;
                ldm_x4(q0, q1, q2, q3, addr);
                bf[bt * 2 + 0][0] = q0; bf[bt * 2 + 0][1] = q2;   // n-rows +0..7
                bf[bt * 2 + 1][0] = q1; bf[bt * 2 + 1][1] = q3;   // n-rows +8..15
            }
            #pragma unroll
            for (int mt = 0; mt < 4; mt++)
                #pragma unroll
                for (int nt = 0; nt < 4; nt++)
                    mma_bf16(acc[mt][nt], af[mt], bf[nt][0], bf[nt][1]);
        }
    }

    // epilogue: add bias, store
    #pragma unroll
    for (int nt = 0; nt < 4; nt++) {
        int col = n0 + wn * 32 + nt * 8 + (lane & 3) * 2;
        float bc0 = __ldg(&b1[col])     + __ldg(&b2[col]);
        float bc1 = __ldg(&b1[col + 1]) + __ldg(&b2[col + 1]);
        #pragma unroll
        for (int mt = 0; mt < 4; mt++) {
            int row = m0 + wm * 64 + mt * 16 + (lane >> 2);
            float2 v0 = make_float2(acc[mt][nt][0] + bc0, acc[mt][nt][1] + bc1);
            float2 v1 = make_float2(acc[mt][nt][2] + bc0, acc[mt][nt][3] + bc1);
            __stcs((float2*)(g_P + (size_t)row * G4 + col), v0);
            __stcs((float2*)(g_P + (size_t)(row + 8) * G4 + col), v1);
        }
    }
}

// ---------------- K2: persistent int8 recurrent kernel (R8 config, best measured) ----------------
__global__ void __launch_bounds__(NTHR, 1) k2_recur() {
    extern __shared__ __align__(16) signed char smem[];
    signed char* shv = smem;                         // 4096: h1q(2048) | h2q(2048)
    signed char* sW1 = smem + 4096;                  // 15 rows * 8KB
    signed char* sW2 = sW1 + W1_CACHE * W1_ROW;      // 6 rows * 16KB

    const int tid  = threadIdx.x;
    const int warp = tid >> 5;
    const int lane = tid & 31;
    const int w    = blockIdx.x * NWARPS + warp;     // owned h-row, both layers

    // pin weight rows in SMEM
    if (warp < W1_CACHE) {
        const int4* src = (const int4*)(g_W1q + (size_t)w * W1_ROW);
        int4* dst = (int4*)(sW1 + (size_t)warp * W1_ROW);
        #pragma unroll
        for (int i = 0; i < 16; i++) dst[lane + i * 32] = src[lane + i * 32];
    }
    if (warp < W2_CACHE) {
        const int4* src = (const int4*)(g_W2q + (size_t)w * W2_ROW);
        int4* dst = (int4*)(sW2 + (size_t)warp * W2_ROW);
        #pragma unroll
        for (int i = 0; i < 32; i++) dst[lane + i * 32] = src[lane + i * 32];
    }

    const float4 fs1 = *(const float4*)(g_s1 + w * 4);
    const float4 fs2 = *(const float4*)(g_s2 + w * 4);
    const float bi = g_b2[w], bf = g_b2[w + H_DIM], bg = g_b2[w + 2*H_DIM], bo = g_b2[w + 3*H_DIM];

    float c1 = 0.f, c2 = 0.f;

    for (int p = 0; p <= T_LEN; p++) {
        // prefetch this step's P early (independent of the staged h)
        float p0 = 0.f, p1 = 0.f, p2 = 0.f, p3 = 0.f;
        if (lane == 0 && p < T_LEN) {
            size_t pb = (size_t)p * G4 + w;
            p0 = __ldcs(&g_P[pb]);
            p1 = __ldcs(&g_P[pb + H_DIM]);
            p2 = __ldcs(&g_P[pb + 2*H_DIM]);
            p3 = __ldcs(&g_P[pb + 3*H_DIM]);
        }

        // stage h vectors: shv[0:2048]=h1q_{p-1}, shv[2048:4096]=h2q_{p-2}
        {
            const int2* s1 = (const int2*)g_h1q[p & 1];
            const int2* s2 = (const int2*)g_h2q[(p + 1) & 1];
            if (tid < 256) ((int2*)shv)[tid] = __ldcg(s1 + tid);
            else           ((int2*)shv)[tid] = __ldcg(s2 + (tid - 256));
        }
        __syncthreads();

        // -------- layer 1, step t = p --------
        if (p < T_LEN) {
            int a0 = 0, a1 = 0, a2 = 0, a3 = 0;
            if (warp < W1_CACHE)
                dot4<4, H_DIM>(sW1 + (size_t)warp * W1_ROW, shv, lane, a0, a1, a2, a3);
            else
                dot4<4, H_DIM>(g_W1q + (size_t)w * W1_ROW, shv, lane, a0, a1, a2, a3);
            a0 = __reduce_add_sync(0xffffffffu, a0);
            a1 = __reduce_add_sync(0xffffffffu, a1);
            a2 = __reduce_add_sync(0xffffffffu, a2);
            a3 = __reduce_add_sync(0xffffffffu, a3);
            if (lane == 0) {
                float gi  = (float)a0 * fs1.x + p0;
                float gf_ = (float)a1 * fs1.y + p1;
                float gg  = (float)a2 * fs1.z + p2;
                float go_ = (float)a3 * fs1.w + p3;
                c1 = sigf(gf_) * c1 + sigf(gi) * tanhfast(gg);
                float h = sigf(go_) * tanhfast(c1);
                g_h1q[(p + 1) & 1][w] = (signed char)__float2int_rn(h * 127.f);
            }
        }

        // -------- layer 2, step t = p-1 (input [h1q_{p-1} ; h2q_{p-2}] = shv) --------
        if (p >= 1) {
            int a0 = 0, a1 = 0, a2 = 0, a3 = 0;
            if (warp < W2_CACHE)
                dot4<8, 2*H_DIM>(sW2 + (size_t)warp * W2_ROW, shv, lane, a0, a1, a2, a3);
            else
                dot4<8, 2*H_DIM>(g_W2q + (size_t)w * W2_ROW, shv, lane, a0, a1, a2, a3);
            a0 = __reduce_add_sync(0xffffffffu, a0);
            a1 = __reduce_add_sync(0xffffffffu, a1);
            a2 = __reduce_add_sync(0xffffffffu, a2);
            a3 = __reduce_add_sync(0xffffffffu, a3);
            if (lane == 0) {
                float gi  = (float)a0 * fs2.x + bi;
                float gf_ = (float)a1 * fs2.y + bf;
                float gg  = (float)a2 * fs2.z + bg;
                float go_ = (float)a3 * fs2.w + bo;
                c2 = sigf(gf_) * c2 + sigf(gi) * tanhfast(gg);
                float h = sigf(go_) * tanhfast(c2);
                g_h2q[p & 1][w] = (signed char)__float2int_rn(h * 127.f);
                if (p == T_LEN) g_h2f[w] = h;
            }
        }

        // -------- grid barrier: fence + atomicAdd arrive, single-word acquire poll --------
        __syncthreads();
        if (tid == 0) {
            __threadfence();                         // release: publish h-state stores
            atomicAdd(&g_count, 1u);
            unsigned tgt = (unsigned)(p + 1) * (unsigned)NCTA;
            while (ld_acq(&g_count) < tgt) { }
        }
        __syncthreads();
    }
}

// ---------------- K3a: tag_space = h2 @ W_out^T + b_out (one block per tag) ----------------
__global__ void k3a(const float* __restrict__ Wout, const float* __restrict__ bout) {
    __shared__ float red[256];
    const int b = blockIdx.x, t = threadIdx.x;
    float acc = 0.f;
    #pragma unroll
    for (int c = 0; c < 2; c++) {
        float4 wv = *(const float4*)(Wout + (size_t)b * H_DIM + c * 1024 + t * 4);
        float4 hv = *(const float4*)(g_h2f + c * 1024 + t * 4);
        acc += wv.x * hv.x + wv.y * hv.y + wv.z * hv.z + wv.w * hv.w;
    }
    red[t] = acc;
    __syncthreads();
    #pragma unroll
    for (int s = 128; s; s >>= 1) {
        if (t < s) red[t] += red[t + s];
        __syncthreads();
    }
    if (t == 0) g_tag[b] = red[0] + bout[b];
}

// ---------------- K3b: log_softmax ----------------
__global__ void k3b(float* __restrict__ out) {
    __shared__ float st[NTAGS];
    __shared__ float m_s, l_s;
    const int t = threadIdx.x;
    float v = g_tag[t];
    st[t] = v;
    __syncthreads();
    if (t == 0) {
        float m = st[0];
        for (int i = 1; i < NTAGS; i++) m = fmaxf(m, st[i]);
        float s = 0.f;
        for (int i = 0; i < NTAGS; i++) s += expf(st[i] - m);
        m_s = m;
        l_s = logf(s);
    }
    __syncthreads();
    out[t] = v - m_s - l_s;
}

// ---------------- launch ----------------
extern "C" void kernel_launch(void* const* d_in, const int* in_sizes, int n_in,
                              void* d_out, int out_size) {
    const float* x    = (const float*)d_in[0];
    const float* Wih1 = (const float*)d_in[1];
    const float* Whh1 = (const float*)d_in[2];
    const float* bih1 = (const float*)d_in[3];
    const float* bhh1 = (const float*)d_in[4];
    const float* Wih2 = (const float*)d_in[5];
    const float* Whh2 = (const float*)d_in[6];
    const float* bih2 = (const float*)d_in[7];
    const float* bhh2 = (const float*)d_in[8];
    const float* Wout = (const float*)d_in[9];
    const float* bout = (const float*)d_in[10];

    cudaFuncSetAttribute(k2_recur, cudaFuncAttributeMaxDynamicSharedMemorySize, SMEM_BYTES);

    k0_quant<<<128, 256>>>(Whh1, Wih2, Whh2, bih2, bhh2);

    dim3 g1(G4 / 128, T_LEN / 128);
    k1_mma<<<g1, 256>>>(x, Wih1, bih1, bhh1);

    k2_recur<<<NCTA, NTHR, SMEM_BYTES>>>();

    k3a<<<NTAGS, 256>>>(Wout, bout);
    k3b<<<1, NTAGS>>>((float*)d_out);
}